// round 6
// baseline (speedup 1.0000x reference)
#include <cuda_runtime.h>
#include <cstdint>

// Problem constants (fixed shapes)
#define PN    100000   // nodes
#define PE    100000   // hyperedges
#define PNNZ  800000   // edges (nnz)
#define PR    4        // ranks
#define PF    64       // features

// ---- scratch (__device__ globals; no allocation). ~21.6 MB total.
// IMPORTANT: these symbols are referenced ONLY from device code. Passing a
// __device__ symbol as a host-side kernel argument yields the host shadow
// address (UB) — that was the cause of the 128 MB checkpoint violations in
// rounds 3-5.
__device__ int    g_is64;
__device__ int    g_cnt_c[PE];
__device__ int    g_cnt_r[PN];
__device__ int    g_ptr_c[PE + 1];
__device__ int    g_ptr_r[PN + 1];
__device__ int    g_cur_c[PE];
__device__ int    g_cur_r[PN];
__device__ __align__(8)  int2   g_e1[PNNZ];   // sorted by col: (row, val bits)      6.4 MB
__device__ __align__(16) float4 g_e2[PNNZ];   // sorted by row: (col bits, s0,s1,s2) 12.8 MB

// he_feat[E][F] lives in the OUTPUT buffer's rank-3 region: out[e*256 + 192..255].
// Valid between pass 1 and pass 2, then overwritten with x at the end.

__device__ __forceinline__ long long load_idx(const void* p, long long i, int is64) {
    if (is64) return ((const long long*)p)[i];
    return (long long)((const int*)p)[i];
}

// --- dtype sniff: int64 LE indices < 2^31 -> every odd 32-bit word is 0.
__global__ void detect_idx_dtype(const void* rows) {
    if (blockIdx.x == 0 && threadIdx.x == 0) {
        const int* p = (const int*)rows;
        int all0 = 1;
        #pragma unroll 4
        for (int i = 0; i < 1024; i++) {
            if (p[2 * i + 1] != 0) { all0 = 0; break; }
        }
        g_is64 = all0;
    }
}

// --- zero both histograms (every replay)
__global__ void zero_counters() {
    int t = blockIdx.x * blockDim.x + threadIdx.x;
    int total = PE + PN;
    for (; t < total; t += gridDim.x * blockDim.x) {
        if (t < PE) g_cnt_c[t] = 0;
        else        g_cnt_r[t - PE] = 0;
    }
}

// --- histogram edges by col and by row
__global__ void histogram_edges(const void* __restrict__ rows,
                                const void* __restrict__ cols) {
    int is64 = g_is64;
    long long e = (long long)blockIdx.x * blockDim.x + threadIdx.x;
    if (e >= PNNZ) return;
    int row = (int)load_idx(rows, e, is64);
    int col = (int)load_idx(cols, e, is64);
    atomicAdd(&g_cnt_c[col], 1);
    atomicAdd(&g_cnt_r[row], 1);
}

// --- single-block exclusive scan of n counters -> ptr (and cursor copy).
// Device-side helper; wrapped by argument-free kernels so that no __device__
// symbol is ever passed from host code.
__device__ __forceinline__ void scan_excl_body(const int* cnt, int* ptr,
                                               int* cur, int n) {
    __shared__ int sm[1024];
    int t = threadIdx.x;
    int chunk = (n + 1023) >> 10;
    int beg = t * chunk;
    int end = beg + chunk; if (end > n) end = n;
    int s = 0;
    for (int i = beg; i < end; i++) s += cnt[i];
    sm[t] = s;
    __syncthreads();
    // Hillis-Steele inclusive scan
    for (int d = 1; d < 1024; d <<= 1) {
        int v = (t >= d) ? sm[t - d] : 0;
        __syncthreads();
        sm[t] += v;
        __syncthreads();
    }
    int run = (t == 0) ? 0 : sm[t - 1];
    for (int i = beg; i < end; i++) {
        int c = cnt[i];
        ptr[i] = run;
        cur[i] = run;
        run += c;
    }
    if (t == 1023) ptr[n] = sm[1023];
}

__global__ void scan_excl_c() { scan_excl_body(g_cnt_c, g_ptr_c, g_cur_c, PE); }
__global__ void scan_excl_r() { scan_excl_body(g_cnt_r, g_ptr_r, g_cur_r, PN); }

// --- scatter edges into both sorted orders; precompute rank scales for pass 2
__global__ void scatter_fill(const float* __restrict__ rank_masks,
                             const float* __restrict__ vals,
                             const void* __restrict__ he_idxs,
                             const void* __restrict__ rows,
                             const void* __restrict__ cols) {
    int is64 = g_is64;
    long long e = (long long)blockIdx.x * blockDim.x + threadIdx.x;
    if (e >= PNNZ) return;
    int row = (int)load_idx(rows, e, is64);
    int col = (int)load_idx(cols, e, is64);
    float v = vals[e];

    int p1 = atomicAdd(&g_cur_c[col], 1);
    g_e1[p1] = make_int2(row, __float_as_int(v));

    long long he = load_idx(he_idxs, col, is64);
    float s0 = rank_masks[(size_t)0 * PE + he] * v;
    float s1 = rank_masks[(size_t)1 * PE + he] * v;
    float s2 = rank_masks[(size_t)2 * PE + he] * v;
    int p2 = atomicAdd(&g_cur_r[row], 1);
    g_e2[p2] = make_float4(__int_as_float(col), s0, s1, s2);
}

// --- pass 1 (gather): he_feat[c, :] = sum over edges in col-bin c of x[row]*val
//     16 threads per hyperedge; each owns one float4 of the 64-float row.
//     he_feat[c] is stored into out[c, 3, :] (rank-3 slot used as scratch).
__global__ void gather_edge_feat(float4* __restrict__ out4,
                                 const float4* __restrict__ x4) {
    long long g = ((long long)blockIdx.x * blockDim.x + threadIdx.x) >> 4;
    int sub = threadIdx.x & 15;
    if (g >= PE) return;
    int beg = g_ptr_c[g];
    int end = g_ptr_c[g + 1];
    float4 acc = make_float4(0.f, 0.f, 0.f, 0.f);
    for (int i = beg; i < end; i++) {
        int2 eRec = g_e1[i];
        float v = __int_as_float(eRec.y);
        float4 a = x4[(long long)eRec.x * 16 + sub];
        acc.x += a.x * v; acc.y += a.y * v; acc.z += a.z * v; acc.w += a.w * v;
    }
    out4[g * 64 + 48 + sub] = acc;   // he_feat scratch = rank-3 region
}

// --- pass 2 (gather): out[n, r, :] = sum over edges in row-bin n of
//     s_r * he_feat[col, :]  (r = 0..2). Reads he_feat from out[col,3,:];
//     writes only ranks 0..2 — disjoint from the scratch region.
__global__ void gather_node_feat(float4* __restrict__ out4) {
    long long n = ((long long)blockIdx.x * blockDim.x + threadIdx.x) >> 4;
    int sub = threadIdx.x & 15;
    if (n >= PN) return;
    int beg = g_ptr_r[n];
    int end = g_ptr_r[n + 1];
    float4 a0 = make_float4(0.f, 0.f, 0.f, 0.f);
    float4 a1 = a0, a2 = a0;
    for (int i = beg; i < end; i++) {
        float4 m = g_e2[i];
        int col = __float_as_int(m.x);
        float4 h = out4[(long long)col * 64 + 48 + sub];
        a0.x += h.x * m.y; a0.y += h.y * m.y; a0.z += h.z * m.y; a0.w += h.w * m.y;
        a1.x += h.x * m.z; a1.y += h.y * m.z; a1.z += h.z * m.z; a1.w += h.w * m.z;
        a2.x += h.x * m.w; a2.y += h.y * m.w; a2.z += h.z * m.w; a2.w += h.w * m.w;
    }
    float4* o = out4 + n * 64;          // 64 float4 per node row (R*F = 256 floats)
    o[sub]      = a0;
    o[16 + sub] = a1;
    o[32 + sub] = a2;
}

// --- final: overwrite rank-3 scratch with x (after pass 2 has consumed it)
__global__ void copy_x_rank3(float4* __restrict__ out4,
                             const float4* __restrict__ x4) {
    long long t = (long long)blockIdx.x * blockDim.x + threadIdx.x;
    long long total = (long long)PN * 16;
    if (t >= total) return;
    long long n = t >> 4;
    int sub = (int)(t & 15);
    out4[n * 64 + 48 + sub] = x4[t];
}

extern "C" void kernel_launch(void* const* d_in, const int* in_sizes, int n_in,
                              void* d_out, int out_size) {
    const float* x          = (const float*)d_in[0];   // (N, F)
    const float* rank_masks = (const float*)d_in[1];   // (R, E)
    const float* vals       = (const float*)d_in[2];   // (NNZ,)
    const void*  he_idxs    = d_in[3];                 // (E,)
    const void*  rows       = d_in[4];                 // (NNZ,)
    const void*  cols       = d_in[5];                 // (NNZ,)
    float4* out4 = (float4*)d_out;                     // (N, R, F)

    detect_idx_dtype<<<1, 32>>>(rows);

    zero_counters<<<((PE + PN) + 255) / 256, 256>>>();

    histogram_edges<<<(PNNZ + 255) / 256, 256>>>(rows, cols);

    scan_excl_c<<<1, 1024>>>();
    scan_excl_r<<<1, 1024>>>();

    scatter_fill<<<(PNNZ + 255) / 256, 256>>>(rank_masks, vals, he_idxs, rows, cols);

    {
        long long threads = (long long)PE * 16;
        gather_edge_feat<<<(int)((threads + 255) / 256), 256>>>(out4, (const float4*)x);
    }
    {
        long long threads = (long long)PN * 16;
        gather_node_feat<<<(int)((threads + 255) / 256), 256>>>(out4);
    }
    {
        long long threads = (long long)PN * 16;
        copy_x_rank3<<<(int)((threads + 255) / 256), 256>>>(out4, (const float4*)x);
    }
}

// round 7
// speedup vs baseline: 3.3485x; 3.3485x over previous
#include <cuda_runtime.h>
#include <cstdint>

// Problem constants (fixed shapes)
#define PN    100000   // nodes
#define PE    100000   // hyperedges
#define PNNZ  800000   // edges (nnz)
#define PR    4        // ranks
#define PF    64       // features

#define NTILE 1024
#define NB_C  ((PE + NTILE - 1) / NTILE)   // 98
#define NB_R  ((PN + NTILE - 1) / NTILE)   // 98

// ---- scratch (__device__ globals; no allocation). ~21.6 MB total.
// RULE (hard-won in rounds 3-6): these symbols are referenced ONLY from
// device code; never passed as host-side kernel arguments (host shadow
// address = UB = 128 MB checkpoint violation).
__device__ int    g_is64;
__device__ int    g_cnt_c[PE];
__device__ int    g_cnt_r[PN];
__device__ int    g_ptr_c[PE + 1];
__device__ int    g_ptr_r[PN + 1];
__device__ int    g_cur_c[PE];
__device__ int    g_cur_r[PN];
__device__ int    g_bsum[NB_C + NB_R];
__device__ __align__(8)  int2   g_e1[PNNZ];   // sorted by col: (row, val bits)      6.4 MB
__device__ __align__(16) float4 g_e2[PNNZ];   // sorted by row: (col bits, s0,s1,s2) 12.8 MB

// he_feat[E][F] lives in the OUTPUT buffer's rank-3 region: out[e*256 + 192..255].
// Valid between pass 1 and pass 2, then overwritten with x at the end.

__device__ __forceinline__ long long load_idx(const void* p, long long i, int is64) {
    if (is64) return ((const long long*)p)[i];
    return (long long)((const int*)p)[i];
}

// --- dtype sniff: int64 LE indices < 2^31 -> every odd 32-bit word is 0.
__global__ void detect_idx_dtype(const void* rows) {
    if (blockIdx.x == 0 && threadIdx.x == 0) {
        const int* p = (const int*)rows;
        int all0 = 1;
        #pragma unroll 4
        for (int i = 0; i < 1024; i++) {
            if (p[2 * i + 1] != 0) { all0 = 0; break; }
        }
        g_is64 = all0;
    }
}

// --- zero both histograms (every replay)
__global__ void zero_counters() {
    int t = blockIdx.x * blockDim.x + threadIdx.x;
    int total = PE + PN;
    for (; t < total; t += gridDim.x * blockDim.x) {
        if (t < PE) g_cnt_c[t] = 0;
        else        g_cnt_r[t - PE] = 0;
    }
}

// --- histogram edges by col and by row
__global__ void histogram_edges(const void* __restrict__ rows,
                                const void* __restrict__ cols) {
    int is64 = g_is64;
    long long e = (long long)blockIdx.x * blockDim.x + threadIdx.x;
    if (e >= PNNZ) return;
    int row = (int)load_idx(rows, e, is64);
    int col = (int)load_idx(cols, e, is64);
    atomicAdd(&g_cnt_c[col], 1);
    atomicAdd(&g_cnt_r[row], 1);
}

// ===================== multi-block exclusive scan =====================
// Phase 1: per-tile scan. Blocks [0, NB_C) handle g_cnt_c; [NB_C, NB_C+NB_R)
// handle g_cnt_r. Local exclusive prefix -> ptr; tile total -> g_bsum.
__global__ void scan_tiles() {
    __shared__ int sm[NTILE];
    int b = blockIdx.x;
    bool isC = (b < NB_C);
    const int* cnt = isC ? g_cnt_c : g_cnt_r;
    int*       ptr = isC ? g_ptr_c : g_ptr_r;
    int n    = isC ? PE : PN;
    int tile = isC ? b : b - NB_C;
    int t = threadIdx.x;
    int i = tile * NTILE + t;
    int v = (i < n) ? cnt[i] : 0;
    sm[t] = v;
    __syncthreads();
    #pragma unroll
    for (int d = 1; d < NTILE; d <<= 1) {
        int u = (t >= d) ? sm[t - d] : 0;
        __syncthreads();
        sm[t] += u;
        __syncthreads();
    }
    if (i < n) ptr[i] = sm[t] - v;          // local exclusive
    if (t == NTILE - 1) g_bsum[b] = sm[t];  // tile total
}

// Phase 2: scan the tile totals. One block; segment [0,128) = c tiles,
// segment [128,256) = r tiles, scanned independently (Hillis-Steele per 128).
__global__ void scan_bsums() {
    __shared__ int sm[256];
    int t = threadIdx.x;          // 0..255
    int seg = t >> 7;             // 0 = c, 1 = r
    int j = t & 127;
    int v = 0;
    if (seg == 0) { if (j < NB_C) v = g_bsum[j]; }
    else          { if (j < NB_R) v = g_bsum[NB_C + j]; }
    sm[t] = v;
    __syncthreads();
    #pragma unroll
    for (int d = 1; d < 128; d <<= 1) {
        int u = (j >= d) ? sm[t - d] : 0;
        __syncthreads();
        sm[t] += u;
        __syncthreads();
    }
    int excl = sm[t] - v;
    if (seg == 0) { if (j < NB_C) g_bsum[j] = excl; }
    else          { if (j < NB_R) g_bsum[NB_C + j] = excl; }
}

// Phase 3: add tile offsets; materialize cursors; set totals.
__global__ void add_offsets() {
    int t = blockIdx.x * blockDim.x + threadIdx.x;
    if (t == 0) { g_ptr_c[PE] = PNNZ; g_ptr_r[PN] = PNNZ; }
    int total = PE + PN;
    for (; t < total; t += gridDim.x * blockDim.x) {
        if (t < PE) {
            int p = g_ptr_c[t] + g_bsum[t / NTILE];
            g_ptr_c[t] = p;
            g_cur_c[t] = p;
        } else {
            int j = t - PE;
            int p = g_ptr_r[j] + g_bsum[NB_C + j / NTILE];
            g_ptr_r[j] = p;
            g_cur_r[j] = p;
        }
    }
}
// ======================================================================

// --- scatter edges into both sorted orders; precompute rank scales for pass 2
__global__ void scatter_fill(const float* __restrict__ rank_masks,
                             const float* __restrict__ vals,
                             const void* __restrict__ he_idxs,
                             const void* __restrict__ rows,
                             const void* __restrict__ cols) {
    int is64 = g_is64;
    long long e = (long long)blockIdx.x * blockDim.x + threadIdx.x;
    if (e >= PNNZ) return;
    int row = (int)load_idx(rows, e, is64);
    int col = (int)load_idx(cols, e, is64);
    float v = vals[e];

    int p1 = atomicAdd(&g_cur_c[col], 1);
    g_e1[p1] = make_int2(row, __float_as_int(v));

    long long he = load_idx(he_idxs, col, is64);
    float s0 = rank_masks[(size_t)0 * PE + he] * v;
    float s1 = rank_masks[(size_t)1 * PE + he] * v;
    float s2 = rank_masks[(size_t)2 * PE + he] * v;
    int p2 = atomicAdd(&g_cur_r[row], 1);
    g_e2[p2] = make_float4(__int_as_float(col), s0, s1, s2);
}

// --- pass 1 (gather): he_feat[c, :] = sum over edges in col-bin c of x[row]*val
//     16 threads per hyperedge; each owns one float4 of the 64-float row.
//     he_feat[c] is stored into out[c, 3, :] (rank-3 slot used as scratch).
__global__ void gather_edge_feat(float4* __restrict__ out4,
                                 const float4* __restrict__ x4) {
    long long g = ((long long)blockIdx.x * blockDim.x + threadIdx.x) >> 4;
    int sub = threadIdx.x & 15;
    if (g >= PE) return;
    int beg = g_ptr_c[g];
    int end = g_ptr_c[g + 1];
    float4 acc = make_float4(0.f, 0.f, 0.f, 0.f);
    for (int i = beg; i < end; i++) {
        int2 eRec = g_e1[i];
        float v = __int_as_float(eRec.y);
        float4 a = x4[(long long)eRec.x * 16 + sub];
        acc.x += a.x * v; acc.y += a.y * v; acc.z += a.z * v; acc.w += a.w * v;
    }
    out4[g * 64 + 48 + sub] = acc;   // he_feat scratch = rank-3 region
}

// --- pass 2 (gather): out[n, r, :] = sum over edges in row-bin n of
//     s_r * he_feat[col, :]  (r = 0..2). Reads he_feat from out[col,3,:];
//     writes only ranks 0..2 — disjoint from the scratch region.
__global__ void gather_node_feat(float4* __restrict__ out4) {
    long long n = ((long long)blockIdx.x * blockDim.x + threadIdx.x) >> 4;
    int sub = threadIdx.x & 15;
    if (n >= PN) return;
    int beg = g_ptr_r[n];
    int end = g_ptr_r[n + 1];
    float4 a0 = make_float4(0.f, 0.f, 0.f, 0.f);
    float4 a1 = a0, a2 = a0;
    for (int i = beg; i < end; i++) {
        float4 m = g_e2[i];
        int col = __float_as_int(m.x);
        float4 h = out4[(long long)col * 64 + 48 + sub];
        a0.x += h.x * m.y; a0.y += h.y * m.y; a0.z += h.z * m.y; a0.w += h.w * m.y;
        a1.x += h.x * m.z; a1.y += h.y * m.z; a1.z += h.z * m.z; a1.w += h.w * m.z;
        a2.x += h.x * m.w; a2.y += h.y * m.w; a2.z += h.z * m.w; a2.w += h.w * m.w;
    }
    float4* o = out4 + n * 64;          // 64 float4 per node row (R*F = 256 floats)
    o[sub]      = a0;
    o[16 + sub] = a1;
    o[32 + sub] = a2;
}

// --- final: overwrite rank-3 scratch with x (after pass 2 has consumed it)
__global__ void copy_x_rank3(float4* __restrict__ out4,
                             const float4* __restrict__ x4) {
    long long t = (long long)blockIdx.x * blockDim.x + threadIdx.x;
    long long total = (long long)PN * 16;
    if (t >= total) return;
    long long n = t >> 4;
    int sub = (int)(t & 15);
    out4[n * 64 + 48 + sub] = x4[t];
}

extern "C" void kernel_launch(void* const* d_in, const int* in_sizes, int n_in,
                              void* d_out, int out_size) {
    const float* x          = (const float*)d_in[0];   // (N, F)
    const float* rank_masks = (const float*)d_in[1];   // (R, E)
    const float* vals       = (const float*)d_in[2];   // (NNZ,)
    const void*  he_idxs    = d_in[3];                 // (E,)
    const void*  rows       = d_in[4];                 // (NNZ,)
    const void*  cols       = d_in[5];                 // (NNZ,)
    float4* out4 = (float4*)d_out;                     // (N, R, F)

    detect_idx_dtype<<<1, 32>>>(rows);

    zero_counters<<<((PE + PN) + 255) / 256, 256>>>();

    histogram_edges<<<(PNNZ + 255) / 256, 256>>>(rows, cols);

    scan_tiles<<<NB_C + NB_R, NTILE>>>();
    scan_bsums<<<1, 256>>>();
    add_offsets<<<((PE + PN) + 255) / 256, 256>>>();

    scatter_fill<<<(PNNZ + 255) / 256, 256>>>(rank_masks, vals, he_idxs, rows, cols);

    {
        long long threads = (long long)PE * 16;
        gather_edge_feat<<<(int)((threads + 255) / 256), 256>>>(out4, (const float4*)x);
    }
    {
        long long threads = (long long)PN * 16;
        gather_node_feat<<<(int)((threads + 255) / 256), 256>>>(out4);
    }
    {
        long long threads = (long long)PN * 16;
        copy_x_rank3<<<(int)((threads + 255) / 256), 256>>>(out4, (const float4*)x);
    }
}

// round 8
// speedup vs baseline: 3.6833x; 1.1000x over previous
#include <cuda_runtime.h>
#include <cstdint>

// Problem constants (fixed shapes)
#define PN    100000   // nodes
#define PE    100000   // hyperedges
#define PNNZ  800000   // edges (nnz)
#define PR    4        // ranks
#define PF    64       // features

#define NTILE 1024
#define NB_C  ((PE + NTILE - 1) / NTILE)   // 98
#define NB_R  ((PN + NTILE - 1) / NTILE)   // 98

// ---- scratch (__device__ globals; no allocation). ~47 MB total.
// RULE (hard-won in rounds 3-6): these symbols are referenced ONLY from
// device code; never passed as host-side kernel arguments (host shadow
// address = UB = 128 MB checkpoint violation).
__device__ int    g_is64;
__device__ int    g_cnt_c[PE];
__device__ int    g_cnt_r[PN];
__device__ int    g_ptr_c[PE + 1];
__device__ int    g_ptr_r[PN + 1];
__device__ int    g_cur_c[PE];
__device__ int    g_cur_r[PN];
__device__ int    g_bsum[NB_C + NB_R];
__device__ __align__(16) float  g_he_feat[(size_t)PE * PF];   // 25.6 MB dense
__device__ __align__(8)  int2   g_e1[PNNZ];   // sorted by col: (row, val bits)      6.4 MB
__device__ __align__(16) float4 g_e2[PNNZ];   // sorted by row: (col bits, s0,s1,s2) 12.8 MB

__device__ __forceinline__ long long load_idx(const void* p, long long i, int is64) {
    if (is64) return ((const long long*)p)[i];
    return (long long)((const int*)p)[i];
}

// --- zero histograms + dtype sniff fused (every replay).
// int64 LE indices < 2^31 -> every odd 32-bit word is 0.
__global__ void zero_and_detect(const void* rows) {
    int t = blockIdx.x * blockDim.x + threadIdx.x;
    if (t == 0) {
        const int* p = (const int*)rows;
        int all0 = 1;
        #pragma unroll 4
        for (int i = 0; i < 1024; i++) {
            if (p[2 * i + 1] != 0) { all0 = 0; break; }
        }
        g_is64 = all0;
    }
    int total = PE + PN;
    for (; t < total; t += gridDim.x * blockDim.x) {
        if (t < PE) g_cnt_c[t] = 0;
        else        g_cnt_r[t - PE] = 0;
    }
}

// --- histogram edges by col and by row
__global__ void histogram_edges(const void* __restrict__ rows,
                                const void* __restrict__ cols) {
    int is64 = g_is64;
    long long e = (long long)blockIdx.x * blockDim.x + threadIdx.x;
    if (e >= PNNZ) return;
    int row = (int)load_idx(rows, e, is64);
    int col = (int)load_idx(cols, e, is64);
    atomicAdd(&g_cnt_c[col], 1);
    atomicAdd(&g_cnt_r[row], 1);
}

// ===================== multi-block exclusive scan =====================
// Phase 1: per-tile scan. Blocks [0, NB_C) handle g_cnt_c; [NB_C, NB_C+NB_R)
// handle g_cnt_r. Local exclusive prefix -> ptr; tile total -> g_bsum.
__global__ void scan_tiles() {
    __shared__ int sm[NTILE];
    int b = blockIdx.x;
    bool isC = (b < NB_C);
    const int* cnt = isC ? g_cnt_c : g_cnt_r;
    int*       ptr = isC ? g_ptr_c : g_ptr_r;
    int n    = isC ? PE : PN;
    int tile = isC ? b : b - NB_C;
    int t = threadIdx.x;
    int i = tile * NTILE + t;
    int v = (i < n) ? cnt[i] : 0;
    sm[t] = v;
    __syncthreads();
    #pragma unroll
    for (int d = 1; d < NTILE; d <<= 1) {
        int u = (t >= d) ? sm[t - d] : 0;
        __syncthreads();
        sm[t] += u;
        __syncthreads();
    }
    if (i < n) ptr[i] = sm[t] - v;          // local exclusive
    if (t == NTILE - 1) g_bsum[b] = sm[t];  // tile total
}

// Phase 2: scan the tile totals. One block; segment [0,128) = c tiles,
// segment [128,256) = r tiles, scanned independently.
__global__ void scan_bsums() {
    __shared__ int sm[256];
    int t = threadIdx.x;          // 0..255
    int seg = t >> 7;             // 0 = c, 1 = r
    int j = t & 127;
    int v = 0;
    if (seg == 0) { if (j < NB_C) v = g_bsum[j]; }
    else          { if (j < NB_R) v = g_bsum[NB_C + j]; }
    sm[t] = v;
    __syncthreads();
    #pragma unroll
    for (int d = 1; d < 128; d <<= 1) {
        int u = (j >= d) ? sm[t - d] : 0;
        __syncthreads();
        sm[t] += u;
        __syncthreads();
    }
    int excl = sm[t] - v;
    if (seg == 0) { if (j < NB_C) g_bsum[j] = excl; }
    else          { if (j < NB_R) g_bsum[NB_C + j] = excl; }
}

// Phase 3: add tile offsets; materialize cursors; set totals.
__global__ void add_offsets() {
    int t = blockIdx.x * blockDim.x + threadIdx.x;
    if (t == 0) { g_ptr_c[PE] = PNNZ; g_ptr_r[PN] = PNNZ; }
    int total = PE + PN;
    for (; t < total; t += gridDim.x * blockDim.x) {
        if (t < PE) {
            int p = g_ptr_c[t] + g_bsum[t / NTILE];
            g_ptr_c[t] = p;
            g_cur_c[t] = p;
        } else {
            int j = t - PE;
            int p = g_ptr_r[j] + g_bsum[NB_C + j / NTILE];
            g_ptr_r[j] = p;
            g_cur_r[j] = p;
        }
    }
}
// ======================================================================

// --- scatter edges into both sorted orders; precompute rank scales for pass 2
__global__ void scatter_fill(const float* __restrict__ rank_masks,
                             const float* __restrict__ vals,
                             const void* __restrict__ he_idxs,
                             const void* __restrict__ rows,
                             const void* __restrict__ cols) {
    int is64 = g_is64;
    long long e = (long long)blockIdx.x * blockDim.x + threadIdx.x;
    if (e >= PNNZ) return;
    int row = (int)load_idx(rows, e, is64);
    int col = (int)load_idx(cols, e, is64);
    float v = vals[e];

    int p1 = atomicAdd(&g_cur_c[col], 1);
    g_e1[p1] = make_int2(row, __float_as_int(v));

    long long he = load_idx(he_idxs, col, is64);
    float s0 = rank_masks[(size_t)0 * PE + he] * v;
    float s1 = rank_masks[(size_t)1 * PE + he] * v;
    float s2 = rank_masks[(size_t)2 * PE + he] * v;
    int p2 = atomicAdd(&g_cur_r[row], 1);
    g_e2[p2] = make_float4(__int_as_float(col), s0, s1, s2);
}

// --- pass 1 (gather): he_feat[c, :] = sum over edges in col-bin c of x[row]*val
//     16 threads per hyperedge; each owns one float4 of the 64-float row.
__global__ void gather_edge_feat(const float4* __restrict__ x4) {
    long long g = ((long long)blockIdx.x * blockDim.x + threadIdx.x) >> 4;
    int sub = threadIdx.x & 15;
    if (g >= PE) return;
    int beg = g_ptr_c[g];
    int end = g_ptr_c[g + 1];
    float4 acc = make_float4(0.f, 0.f, 0.f, 0.f);
    #pragma unroll 2
    for (int i = beg; i < end; i++) {
        int2 eRec = g_e1[i];
        float v = __int_as_float(eRec.y);
        float4 a = x4[(long long)eRec.x * 16 + sub];
        acc.x += a.x * v; acc.y += a.y * v; acc.z += a.z * v; acc.w += a.w * v;
    }
    ((float4*)g_he_feat)[g * 16 + sub] = acc;   // dense, coalesced
}

// --- pass 2 (gather, fused with rank-3 init):
//     out[n, r, :] = sum over edges in row-bin n of s_r * he_feat[col, :] (r=0..2)
//     out[n, 3, :] = x[n, :]   -- full 1 KB node row written contiguously.
__global__ void gather_node_feat(float4* __restrict__ out4,
                                 const float4* __restrict__ x4) {
    long long n = ((long long)blockIdx.x * blockDim.x + threadIdx.x) >> 4;
    int sub = threadIdx.x & 15;
    if (n >= PN) return;
    int beg = g_ptr_r[n];
    int end = g_ptr_r[n + 1];
    const float4* hf4 = (const float4*)g_he_feat;
    float4 a0 = make_float4(0.f, 0.f, 0.f, 0.f);
    float4 a1 = a0, a2 = a0;
    #pragma unroll 2
    for (int i = beg; i < end; i++) {
        float4 m = g_e2[i];
        int col = __float_as_int(m.x);
        float4 h = hf4[(long long)col * 16 + sub];
        a0.x += h.x * m.y; a0.y += h.y * m.y; a0.z += h.z * m.y; a0.w += h.w * m.y;
        a1.x += h.x * m.z; a1.y += h.y * m.z; a1.z += h.z * m.z; a1.w += h.w * m.z;
        a2.x += h.x * m.w; a2.y += h.y * m.w; a2.z += h.z * m.w; a2.w += h.w * m.w;
    }
    float4* o = out4 + n * 64;          // 64 float4 per node row (R*F = 256 floats)
    o[sub]      = a0;
    o[16 + sub] = a1;
    o[32 + sub] = a2;
    o[48 + sub] = x4[n * 16 + sub];     // fused rank-3 = x
}

extern "C" void kernel_launch(void* const* d_in, const int* in_sizes, int n_in,
                              void* d_out, int out_size) {
    const float* x          = (const float*)d_in[0];   // (N, F)
    const float* rank_masks = (const float*)d_in[1];   // (R, E)
    const float* vals       = (const float*)d_in[2];   // (NNZ,)
    const void*  he_idxs    = d_in[3];                 // (E,)
    const void*  rows       = d_in[4];                 // (NNZ,)
    const void*  cols       = d_in[5];                 // (NNZ,)
    float4* out4 = (float4*)d_out;                     // (N, R, F)

    zero_and_detect<<<((PE + PN) + 255) / 256, 256>>>(rows);

    histogram_edges<<<(PNNZ + 255) / 256, 256>>>(rows, cols);

    scan_tiles<<<NB_C + NB_R, NTILE>>>();
    scan_bsums<<<1, 256>>>();
    add_offsets<<<((PE + PN) + 255) / 256, 256>>>();

    scatter_fill<<<(PNNZ + 255) / 256, 256>>>(rank_masks, vals, he_idxs, rows, cols);

    {
        long long threads = (long long)PE * 16;
        gather_edge_feat<<<(int)((threads + 255) / 256), 256>>>((const float4*)x);
    }
    {
        long long threads = (long long)PN * 16;
        gather_node_feat<<<(int)((threads + 255) / 256), 256>>>(out4, (const float4*)x);
    }
}